// round 2
// baseline (speedup 1.0000x reference)
#include <cuda_runtime.h>

#define BATCH 8
#define NNODE 4096
#define DIM   256
#define TOPK  8

static __device__ __forceinline__ float neg_inf() { return __int_as_float(0xff800000); }

// Scratch (device globals; no dynamic allocation allowed)
__device__ float g_XnT[BATCH * DIM * NNODE];   // [b][d][n]  normalized, transposed
__device__ int   g_topk[BATCH * NNODE * TOPK]; // [b][n][k]
__device__ float g_Wt[DIM * DIM];              // [d][e] = W[e][d]

// ---------------------------------------------------------------------------
// Kernel 1: row L2-normalize + transpose into g_XnT
// block: 256 threads, 32 rows; grid (N/32, B)
// ---------------------------------------------------------------------------
__global__ void k_norm_transpose(const float* __restrict__ X) {
    __shared__ float s_t[32][257];
    const int b  = blockIdx.y;
    const int n0 = blockIdx.x * 32;
    const int t  = threadIdx.x;
    const int w  = t >> 5, lane = t & 31;
    const float* Xb = X + (b * NNODE + n0) * DIM;

    for (int rr = 0; rr < 4; rr++) {
        const int r = w * 4 + rr;
        const float4* row = (const float4*)(Xb + r * DIM);
        float4 v0 = row[lane];
        float4 v1 = row[lane + 32];
        float ss = v0.x*v0.x + v0.y*v0.y + v0.z*v0.z + v0.w*v0.w
                 + v1.x*v1.x + v1.y*v1.y + v1.z*v1.z + v1.w*v1.w;
        #pragma unroll
        for (int off = 16; off >= 1; off >>= 1)
            ss += __shfl_xor_sync(0xFFFFFFFFu, ss, off);
        const float inv = 1.0f / fmaxf(sqrtf(ss), 1e-12f);
        const int c0 = lane * 4;
        s_t[r][c0+0] = v0.x*inv; s_t[r][c0+1] = v0.y*inv;
        s_t[r][c0+2] = v0.z*inv; s_t[r][c0+3] = v0.w*inv;
        s_t[r][128+c0+0] = v1.x*inv; s_t[r][128+c0+1] = v1.y*inv;
        s_t[r][128+c0+2] = v1.z*inv; s_t[r][128+c0+3] = v1.w*inv;
    }
    __syncthreads();
    float* outp = g_XnT + b * (DIM * NNODE);
    #pragma unroll
    for (int s = 0; s < 32; s++) {
        const int lin = t + 256 * s;      // 8192 elements
        const int d = lin >> 5;
        const int r = lin & 31;
        outp[d * NNODE + n0 + r] = s_t[r][d];
    }
}

// ---------------------------------------------------------------------------
// Kernel 1b: transpose W (one-time, tiny)
// ---------------------------------------------------------------------------
__global__ void k_wt(const float* __restrict__ W) {
    __shared__ float s[32][33];
    const int e0 = blockIdx.x * 32, d0 = blockIdx.y * 32;
    const int tx = threadIdx.x, ty = threadIdx.y;
    for (int i = ty; i < 32; i += 8) s[i][tx] = W[(e0 + i) * DIM + d0 + tx];
    __syncthreads();
    for (int i = ty; i < 32; i += 8) g_Wt[(d0 + i) * DIM + e0 + tx] = s[tx][i];
}

// ---------------------------------------------------------------------------
// Kernel 2: fused sim GEMM (Xn·Xn^T) + streaming per-row top-8
// 128x128 block tile, 8x8 microtile, K-chunks of 64. grid (N/128, B), 256 thr.
// smem: As[64][132] + Bs[64][132] + topv[128][8] + topi[128][8] + thr[128]
// ---------------------------------------------------------------------------
#define ASTR 132
#define K2_SMEM ((2*64*ASTR + 128*8) * 4 + 128*8*4 + 128*4)

__global__ __launch_bounds__(256, 2) void k_sim_topk() {
    extern __shared__ float smem[];
    float* As    = smem;
    float* Bs    = As + 64 * ASTR;
    float* topv  = Bs + 64 * ASTR;
    int*   topi  = (int*)(topv + 128 * 8);
    float* thr_s = (float*)(topi + 128 * 8);

    const int b  = blockIdx.y;
    const int i0 = blockIdx.x * 128;
    const float* Xt = g_XnT + b * (DIM * NNODE);
    const int t  = threadIdx.x;
    const int tx = t & 15, ty = t >> 4;
    const int lane16 = t & 15;
    const unsigned hmask = (t & 16) ? 0xFFFF0000u : 0x0000FFFFu;

    for (int i = t; i < 128 * 8; i += 256) { topv[i] = neg_inf(); topi[i] = 0x7FFFFFFF; }
    if (t < 128) thr_s[t] = neg_inf();
    __syncthreads();

    for (int j0 = 0; j0 < NNODE; j0 += 128) {
        float acc[8][8];
        #pragma unroll
        for (int v = 0; v < 8; v++)
            #pragma unroll
            for (int u = 0; u < 8; u++) acc[v][u] = 0.0f;

        for (int kc = 0; kc < DIM; kc += 64) {
            __syncthreads();
            #pragma unroll
            for (int s = 0; s < 8; s++) {
                const int lin = t + 256 * s;          // 2048 float4 slots
                const int m4 = (lin & 31) * 4;
                const int kk = lin >> 5;
                const float* src = Xt + (kc + kk) * NNODE;
                *(float4*)(As + kk * ASTR + m4) = *(const float4*)(src + i0 + m4);
                *(float4*)(Bs + kk * ASTR + m4) = *(const float4*)(src + j0 + m4);
            }
            __syncthreads();
            #pragma unroll 4
            for (int kk = 0; kk < 64; kk++) {
                const float4 a0 = *(const float4*)(As + kk * ASTR + ty * 8);
                const float4 a1 = *(const float4*)(As + kk * ASTR + ty * 8 + 4);
                const float4 b0 = *(const float4*)(Bs + kk * ASTR + tx * 8);
                const float4 b1 = *(const float4*)(Bs + kk * ASTR + tx * 8 + 4);
                const float av[8] = {a0.x,a0.y,a0.z,a0.w,a1.x,a1.y,a1.z,a1.w};
                const float bv[8] = {b0.x,b0.y,b0.z,b0.w,b1.x,b1.y,b1.z,b1.w};
                #pragma unroll
                for (int v = 0; v < 8; v++)
                    #pragma unroll
                    for (int u = 0; u < 8; u++)
                        acc[v][u] = fmaf(av[v], bv[u], acc[v][u]);
            }
        }

        // ---- top-8 merge (half-warp cooperative, threshold-gated) ----
        const int rbase = ty * 8;
        #pragma unroll
        for (int v = 0; v < 8; v++) {
            const int row = rbase + v;
            const float thr = thr_s[row];
            bool any = false;
            #pragma unroll
            for (int u = 0; u < 8; u++) any = any || (acc[v][u] > thr);
            if (__ballot_sync(hmask, any) == 0) continue;

            float cv[9]; int ci[9];
            #pragma unroll
            for (int u = 0; u < 8; u++) { cv[u] = acc[v][u]; ci[u] = j0 + tx * 8 + u; }
            if (lane16 < 8) { cv[8] = topv[row * 8 + lane16]; ci[8] = topi[row * 8 + lane16]; }
            else            { cv[8] = neg_inf();              ci[8] = 0x7FFFFFFF; }

            float keepv = 0.0f; int keepi = 0;
            #pragma unroll
            for (int it = 0; it < 8; it++) {
                float bvv = cv[0]; int bii = ci[0]; int bsl = 0;
                #pragma unroll
                for (int c = 1; c < 9; c++) {
                    const bool better = (cv[c] > bvv) || (cv[c] == bvv && ci[c] < bii);
                    if (better) { bvv = cv[c]; bii = ci[c]; bsl = c; }
                }
                float rv = bvv; int ri = bii;
                #pragma unroll
                for (int off = 8; off >= 1; off >>= 1) {
                    const float ov = __shfl_xor_sync(hmask, rv, off);
                    const int   oi = __shfl_xor_sync(hmask, ri, off);
                    if (ov > rv || (ov == rv && oi < ri)) { rv = ov; ri = oi; }
                }
                if (bii == ri) {  // this lane contributed the winner: remove it
                    #pragma unroll
                    for (int c = 0; c < 9; c++)
                        if (c == bsl) { cv[c] = neg_inf(); ci[c] = 0x7FFFFFFF; }
                }
                if (lane16 == it) { keepv = rv; keepi = ri; }
            }
            if (lane16 < 8) { topv[row * 8 + lane16] = keepv; topi[row * 8 + lane16] = keepi; }
            if (lane16 == 7) thr_s[row] = keepv;
        }
    }
    __syncthreads();
    for (int i = t; i < 128 * TOPK; i += 256)
        g_topk[(b * NNODE + i0) * TOPK + i] = topi[i];
}

// ---------------------------------------------------------------------------
// Kernel 3: gather-mean msg -> Y = msg·W^T + b -> Z = X + Y -> LayerNorm
// 32 rows per block, 256 threads. grid (N/32, B).
// smem: msg[32][260] + Ws[32][260] + idx[256]
// ---------------------------------------------------------------------------
#define K3_SMEM ((2 * 32 * 260) * 4 + 256 * 4)

__global__ __launch_bounds__(256, 2) void k_msg_gemm_ln(
    const float* __restrict__ X, const float* __restrict__ bias,
    const float* __restrict__ gamma, const float* __restrict__ beta,
    float* __restrict__ outp)
{
    extern __shared__ float smem[];
    float* msg = smem;                  // 32*260
    float* Ws  = msg + 32 * 260;        // 32*260
    int* sidx  = (int*)(Ws + 32 * 260); // 256

    const int b = blockIdx.y, n0 = blockIdx.x * 32;
    const int t = threadIdx.x, w = t >> 5, lane = t & 31;
    const float* Xb = X + b * (NNODE * DIM);

    sidx[t] = g_topk[(b * NNODE + n0) * TOPK + t];
    __syncthreads();

    // gather-mean: warp w handles rows w*4 .. w*4+3
    for (int rr = 0; rr < 4; rr++) {
        const int r = w * 4 + rr;
        float4 a0 = make_float4(0,0,0,0), a1 = make_float4(0,0,0,0);
        #pragma unroll
        for (int nb = 0; nb < 8; nb++) {
            const int j = sidx[r * 8 + nb];
            const float4* src = (const float4*)(Xb + j * DIM);
            const float4 v0 = src[lane], v1 = src[lane + 32];
            a0.x += v0.x; a0.y += v0.y; a0.z += v0.z; a0.w += v0.w;
            a1.x += v1.x; a1.y += v1.y; a1.z += v1.z; a1.w += v1.w;
        }
        const float sc = 0.125f;
        a0.x *= sc; a0.y *= sc; a0.z *= sc; a0.w *= sc;
        a1.x *= sc; a1.y *= sc; a1.z *= sc; a1.w *= sc;
        *(float4*)(msg + r * 260 + lane * 4)       = a0;
        *(float4*)(msg + r * 260 + 128 + lane * 4) = a1;
    }

    const int tx = t & 15, ty = t >> 4;
    const int r0 = ty * 2;
    float acc0[16], acc1[16];
    #pragma unroll
    for (int i = 0; i < 16; i++) { acc0[i] = 0.0f; acc1[i] = 0.0f; }

    for (int kc = 0; kc < DIM; kc += 32) {
        __syncthreads();
        #pragma unroll
        for (int s = 0; s < 8; s++) {
            const int lin = t + 256 * s;   // 2048 float4 slots
            const int e4 = (lin & 63) * 4;
            const int dd = lin >> 6;
            *(float4*)(Ws + dd * 260 + e4) = *(const float4*)(g_Wt + (kc + dd) * DIM + e4);
        }
        __syncthreads();
        #pragma unroll 4
        for (int kk = 0; kk < 32; kk++) {
            const float m0 = msg[r0 * 260 + kc + kk];
            const float m1 = msg[(r0 + 1) * 260 + kc + kk];
            #pragma unroll
            for (int q = 0; q < 4; q++) {
                const float4 wv = *(const float4*)(Ws + kk * 260 + q * 64 + tx * 4);
                acc0[q*4+0] = fmaf(m0, wv.x, acc0[q*4+0]);
                acc0[q*4+1] = fmaf(m0, wv.y, acc0[q*4+1]);
                acc0[q*4+2] = fmaf(m0, wv.z, acc0[q*4+2]);
                acc0[q*4+3] = fmaf(m0, wv.w, acc0[q*4+3]);
                acc1[q*4+0] = fmaf(m1, wv.x, acc1[q*4+0]);
                acc1[q*4+1] = fmaf(m1, wv.y, acc1[q*4+1]);
                acc1[q*4+2] = fmaf(m1, wv.z, acc1[q*4+2]);
                acc1[q*4+3] = fmaf(m1, wv.w, acc1[q*4+3]);
            }
        }
    }

    // epilogue: bias + residual + LayerNorm (two-pass, half-warp reductions)
    float z0[16], z1[16];
    #pragma unroll
    for (int q = 0; q < 4; q++) {
        const int e = q * 64 + tx * 4;
        const float4 bb = *(const float4*)(bias + e);
        const float4 x0 = *(const float4*)(Xb + (n0 + r0) * DIM + e);
        const float4 x1 = *(const float4*)(Xb + (n0 + r0 + 1) * DIM + e);
        z0[q*4+0] = acc0[q*4+0] + bb.x + x0.x;
        z0[q*4+1] = acc0[q*4+1] + bb.y + x0.y;
        z0[q*4+2] = acc0[q*4+2] + bb.z + x0.z;
        z0[q*4+3] = acc0[q*4+3] + bb.w + x0.w;
        z1[q*4+0] = acc1[q*4+0] + bb.x + x1.x;
        z1[q*4+1] = acc1[q*4+1] + bb.y + x1.y;
        z1[q*4+2] = acc1[q*4+2] + bb.z + x1.z;
        z1[q*4+3] = acc1[q*4+3] + bb.w + x1.w;
    }
    const unsigned hmask = (t & 16) ? 0xFFFF0000u : 0x0000FFFFu;
    float s0 = 0.0f, s1 = 0.0f;
    #pragma unroll
    for (int i = 0; i < 16; i++) { s0 += z0[i]; s1 += z1[i]; }
    #pragma unroll
    for (int off = 8; off >= 1; off >>= 1) {
        s0 += __shfl_xor_sync(hmask, s0, off);
        s1 += __shfl_xor_sync(hmask, s1, off);
    }
    const float mu0 = s0 * (1.0f / 256.0f), mu1 = s1 * (1.0f / 256.0f);
    float q0 = 0.0f, q1 = 0.0f;
    #pragma unroll
    for (int i = 0; i < 16; i++) {
        const float d0 = z0[i] - mu0; q0 += d0 * d0;
        const float d1 = z1[i] - mu1; q1 += d1 * d1;
    }
    #pragma unroll
    for (int off = 8; off >= 1; off >>= 1) {
        q0 += __shfl_xor_sync(hmask, q0, off);
        q1 += __shfl_xor_sync(hmask, q1, off);
    }
    const float is0 = rsqrtf(q0 * (1.0f / 256.0f) + 1e-5f);
    const float is1 = rsqrtf(q1 * (1.0f / 256.0f) + 1e-5f);
    #pragma unroll
    for (int q = 0; q < 4; q++) {
        const int e = q * 64 + tx * 4;
        const float4 g  = *(const float4*)(gamma + e);
        const float4 be = *(const float4*)(beta + e);
        float4 o0, o1;
        o0.x = (z0[q*4+0] - mu0) * is0 * g.x + be.x;
        o0.y = (z0[q*4+1] - mu0) * is0 * g.y + be.y;
        o0.z = (z0[q*4+2] - mu0) * is0 * g.z + be.z;
        o0.w = (z0[q*4+3] - mu0) * is0 * g.w + be.w;
        o1.x = (z1[q*4+0] - mu1) * is1 * g.x + be.x;
        o1.y = (z1[q*4+1] - mu1) * is1 * g.y + be.y;
        o1.z = (z1[q*4+2] - mu1) * is1 * g.z + be.z;
        o1.w = (z1[q*4+3] - mu1) * is1 * g.w + be.w;
        *(float4*)(outp + (b * NNODE + n0 + r0) * DIM + e)     = o0;
        *(float4*)(outp + (b * NNODE + n0 + r0 + 1) * DIM + e) = o1;
    }
}

// ---------------------------------------------------------------------------
extern "C" void kernel_launch(void* const* d_in, const int* in_sizes, int n_in,
                              void* d_out, int out_size) {
    const float* X     = (const float*)d_in[0];
    const float* W     = (const float*)d_in[1];
    const float* bias  = (const float*)d_in[2];
    const float* gamma = (const float*)d_in[3];
    const float* beta  = (const float*)d_in[4];
    float* outp = (float*)d_out;

    static bool s_attr_done = false;
    if (!s_attr_done) {
        cudaFuncSetAttribute(k_sim_topk, cudaFuncAttributeMaxDynamicSharedMemorySize, K2_SMEM);
        cudaFuncSetAttribute(k_msg_gemm_ln, cudaFuncAttributeMaxDynamicSharedMemorySize, K3_SMEM);
        s_attr_done = true;
    }

    k_norm_transpose<<<dim3(NNODE / 32, BATCH), 256>>>(X);
    k_wt<<<dim3(DIM / 32, DIM / 32), dim3(32, 8)>>>(W);
    k_sim_topk<<<dim3(NNODE / 128, BATCH), 256, K2_SMEM>>>();
    k_msg_gemm_ln<<<dim3(NNODE / 32, BATCH), 256, K3_SMEM>>>(X, bias, gamma, beta, outp);
}

// round 5
// speedup vs baseline: 3.5023x; 3.5023x over previous
#include <cuda_runtime.h>
#include <cuda_fp16.h>
#include <cstdint>

#define BATCH 8
#define NNODE 4096
#define DIM   256
#define TOPK  8
#define NJT   32                 // j tiles of 128

static __device__ __forceinline__ float neg_inf() { return __int_as_float(0xff800000); }

// ---------------- device scratch ----------------
__device__ __half g_Xhi[BATCH * NNODE * DIM];
__device__ __half g_Xlo[BATCH * NNODE * DIM];
__device__ int    g_topk[BATCH * NNODE * TOPK];
__device__ float  g_Wt[DIM * DIM];

// ---------------- helpers ----------------
__device__ __forceinline__ uint32_t smem_to_u32(const void* p) {
    uint32_t a;
    asm("{ .reg .u64 t; cvta.to.shared.u64 t, %1; cvt.u32.u64 %0, t; }" : "=r"(a) : "l"(p));
    return a;
}

#define CP_ASYNC16(dst, src) \
    asm volatile("cp.async.cg.shared.global [%0], [%1], 16;" :: "r"((uint32_t)(dst)), "l"(src) : "memory")
#define CP_ASYNC_COMMIT() asm volatile("cp.async.commit_group;" ::: "memory")
#define CP_ASYNC_WAIT0()  asm volatile("cp.async.wait_group 0;" ::: "memory")
#define CP_ASYNC_WAIT1()  asm volatile("cp.async.wait_group 1;" ::: "memory")

#define LDSM_X4(R0, R1, R2, R3, ADDR) \
    asm volatile("ldmatrix.sync.aligned.m8n8.x4.shared.b16 {%0,%1,%2,%3}, [%4];" \
                 : "=r"(R0), "=r"(R1), "=r"(R2), "=r"(R3) : "r"((uint32_t)(ADDR)))

#define MMA16816(C, A, B0, B1) \
    asm volatile("mma.sync.aligned.m16n8k16.row.col.f32.f16.f16.f32 " \
                 "{%0,%1,%2,%3}, {%4,%5,%6,%7}, {%8,%9}, {%0,%1,%2,%3};" \
                 : "+f"((C)[0]), "+f"((C)[1]), "+f"((C)[2]), "+f"((C)[3]) \
                 : "r"((A)[0]), "r"((A)[1]), "r"((A)[2]), "r"((A)[3]), "r"(B0), "r"(B1))

// ---------------------------------------------------------------------------
// Kernel 1: L2-normalize rows + split into f16 hi/lo
// ---------------------------------------------------------------------------
__global__ void k_norm_split(const float* __restrict__ X) {
    const int gr = blockIdx.x * 8 + (threadIdx.x >> 5);
    const int lane = threadIdx.x & 31;
    const float4* p = (const float4*)(X + (size_t)gr * DIM);
    float4 v0 = p[lane * 2], v1 = p[lane * 2 + 1];
    float ss = v0.x*v0.x + v0.y*v0.y + v0.z*v0.z + v0.w*v0.w
             + v1.x*v1.x + v1.y*v1.y + v1.z*v1.z + v1.w*v1.w;
    #pragma unroll
    for (int off = 16; off >= 1; off >>= 1) ss += __shfl_xor_sync(0xFFFFFFFFu, ss, off);
    const float inv = 1.0f / fmaxf(sqrtf(ss), 1e-12f);
    float v[8] = {v0.x*inv, v0.y*inv, v0.z*inv, v0.w*inv, v1.x*inv, v1.y*inv, v1.z*inv, v1.w*inv};
    uint32_t hp[4], lp[4];
    #pragma unroll
    for (int k = 0; k < 4; k++) {
        __half h0 = __float2half_rn(v[2*k]),   h1 = __float2half_rn(v[2*k+1]);
        __half l0 = __float2half_rn(v[2*k]   - __half2float(h0));
        __half l1 = __float2half_rn(v[2*k+1] - __half2float(h1));
        __half2 hh = __halves2half2(h0, h1), ll = __halves2half2(l0, l1);
        hp[k] = *(uint32_t*)&hh; lp[k] = *(uint32_t*)&ll;
    }
    const size_t o = (size_t)gr * DIM + lane * 8;
    *(uint4*)(g_Xhi + o) = make_uint4(hp[0], hp[1], hp[2], hp[3]);
    *(uint4*)(g_Xlo + o) = make_uint4(lp[0], lp[1], lp[2], lp[3]);
}

// ---------------------------------------------------------------------------
// Kernel 1b: transpose W
// ---------------------------------------------------------------------------
__global__ void k_wt(const float* __restrict__ W) {
    __shared__ float s[32][33];
    const int e0 = blockIdx.x * 32, d0 = blockIdx.y * 32;
    const int tx = threadIdx.x, ty = threadIdx.y;
    for (int i = ty; i < 32; i += 8) s[i][tx] = W[(e0 + i) * DIM + d0 + tx];
    __syncthreads();
    for (int i = ty; i < 32; i += 8) g_Wt[(d0 + i) * DIM + e0 + tx] = s[tx][i];
}

// ---------------------------------------------------------------------------
// Kernel 2: mma.sync (m16n8k16 f16) sim GEMM + fused per-row top-8
//   sim = Ahi*Bhi + Alo*Bhi + Ahi*Blo  (hi/lo f16 split, f32 accumulate)
//   CTA: 128 i-rows x all j; 8 warps as 4(m) x 2(n); warp tile 32x64.
//   smem: A hi/lo resident (stride 264 f16); B double-buffered chunks
//   (128 rows x 128 f16, stride 136). 4 stages per j-tile:
//   (Bhi,k0):AhiB+AloB  (Blo,k0):AhiB  (Bhi,k1):AhiB+AloB  (Blo,k1):AhiB
// ---------------------------------------------------------------------------
#define SA 264
#define SB 136
#define A_BYTES (128 * SA * 2)          // 67584
#define B_BYTES (128 * SB * 2)          // 34816
#define OFF_AHI 0
#define OFF_ALO A_BYTES
#define OFF_B0  (2 * A_BYTES)
#define OFF_B1  (2 * A_BYTES + B_BYTES)
#define K2_SMEM (2 * A_BYTES + 2 * B_BYTES)   // 204800

__global__ __launch_bounds__(256, 1) void k_sim_topk() {
    extern __shared__ char smem[];
    const uint32_t sb = smem_to_u32(smem);
    const int t = threadIdx.x, lane = t & 31, wid = t >> 5;
    const int b = blockIdx.y, i0 = blockIdx.x * 128;
    const int wm = wid >> 1, wn = wid & 1;

    // ---- A (hi+lo) -> smem ----
    {
        const __half* srch = g_Xhi + ((size_t)(b * NNODE) + i0) * DIM;
        const __half* srcl = g_Xlo + ((size_t)(b * NNODE) + i0) * DIM;
        #pragma unroll
        for (int s = 0; s < 16; s++) {
            const int p = t + 256 * s;          // 4096 pieces of 16B
            const int row = p >> 5, pc = p & 31;
            CP_ASYNC16(sb + OFF_AHI + row * 528 + pc * 16, srch + (size_t)row * DIM + pc * 8);
            CP_ASYNC16(sb + OFF_ALO + row * 528 + pc * 16, srcl + (size_t)row * DIM + pc * 8);
        }
    }

    auto prefetch = [&](int st) {
        const int sub = st & 3, jt = st >> 2, kc = sub >> 1;
        const __half* g = (sub & 1) ? g_Xlo : g_Xhi;
        const __half* src = g + ((size_t)(b * NNODE) + jt * 128) * DIM + kc * 128;
        const uint32_t dst = sb + ((st & 1) ? OFF_B1 : OFF_B0);
        #pragma unroll
        for (int s = 0; s < 8; s++) {
            const int p = t + 256 * s;          // 2048 pieces
            const int row = p >> 4, pc = p & 15;
            CP_ASYNC16(dst + row * 272 + pc * 16, src + (size_t)row * DIM + pc * 8);
        }
    };

    prefetch(0);
    CP_ASYNC_COMMIT();   // group: A + stage0

    // lane-constant ldmatrix bases (byte offsets); strides give conflict-free phases
    const uint32_t aRowB = (uint32_t)(wm * 32 + (lane & 15)) * 528 + ((lane >> 4) << 4);
    const uint32_t bRowB = (uint32_t)((lane & 7) + ((lane >> 4) << 3) + wn * 64) * 272
                         + ((lane & 8) ? 16 : 0);

    float acc[2][8][4];
    #pragma unroll
    for (int mf = 0; mf < 2; mf++)
        #pragma unroll
        for (int nn = 0; nn < 8; nn++)
            #pragma unroll
            for (int c = 0; c < 4; c++) acc[mf][nn][c] = 0.0f;

    float tv[4][8]; int ti[4][8];
    #pragma unroll
    for (int r = 0; r < 4; r++)
        #pragma unroll
        for (int k = 0; k < 8; k++) { tv[r][k] = neg_inf(); ti[r][k] = 0x7FFFFFFF; }

    for (int st = 0; st < 4 * NJT; st++) {
        if (st + 1 < 4 * NJT) { prefetch(st + 1); CP_ASYNC_COMMIT(); CP_ASYNC_WAIT1(); }
        else                  { CP_ASYNC_WAIT0(); }
        __syncthreads();

        const int sub = st & 3, kc = sub >> 1;
        const bool dual = (sub & 1) == 0;       // hi-stage: Ahi*B and Alo*B
        const uint32_t bbuf = sb + ((st & 1) ? OFF_B1 : OFF_B0);
        const int kbyte0 = kc * 256;            // kc*128 f16 -> bytes

        #pragma unroll
        for (int k16 = 0; k16 < 8; k16++) {
            uint32_t Bf[4][4];
            const uint32_t bk = bbuf + bRowB + k16 * 32;
            #pragma unroll
            for (int nf = 0; nf < 4; nf++)
                LDSM_X4(Bf[nf][0], Bf[nf][1], Bf[nf][2], Bf[nf][3], bk + nf * (16 * 272));

            const uint32_t akb = aRowB + kbyte0 + k16 * 32;
            uint32_t Af[2][4];
            #pragma unroll
            for (int mf = 0; mf < 2; mf++)
                LDSM_X4(Af[mf][0], Af[mf][1], Af[mf][2], Af[mf][3],
                        sb + OFF_AHI + akb + mf * (16 * 528));
            #pragma unroll
            for (int mf = 0; mf < 2; mf++)
                #pragma unroll
                for (int nf = 0; nf < 4; nf++) {
                    MMA16816(acc[mf][nf * 2],     Af[mf], Bf[nf][0], Bf[nf][1]);
                    MMA16816(acc[mf][nf * 2 + 1], Af[mf], Bf[nf][2], Bf[nf][3]);
                }
            if (dual) {
                uint32_t Al[2][4];
                #pragma unroll
                for (int mf = 0; mf < 2; mf++)
                    LDSM_X4(Al[mf][0], Al[mf][1], Al[mf][2], Al[mf][3],
                            sb + OFF_ALO + akb + mf * (16 * 528));
                #pragma unroll
                for (int mf = 0; mf < 2; mf++)
                    #pragma unroll
                    for (int nf = 0; nf < 4; nf++) {
                        MMA16816(acc[mf][nf * 2],     Al[mf], Bf[nf][0], Bf[nf][1]);
                        MMA16816(acc[mf][nf * 2 + 1], Al[mf], Bf[nf][2], Bf[nf][3]);
                    }
            }
        }
        __syncthreads();

        if (sub == 3) {
            // ---- extract this j-tile into per-lane top-8 lists, reset acc ----
            const int j0 = (st >> 2) * 128;
            #pragma unroll
            for (int mf = 0; mf < 2; mf++)
                #pragma unroll
                for (int h = 0; h < 2; h++) {
                    const int rr = mf * 2 + h;
                    #pragma unroll
                    for (int nn = 0; nn < 8; nn++)
                        #pragma unroll
                        for (int c = 0; c < 2; c++) {
                            const float v = acc[mf][nn][h * 2 + c];
                            if (v > tv[rr][7]) {   // strict >: earlier j wins ties
                                const int j = j0 + wn * 64 + nn * 8 + (lane & 3) * 2 + c;
                                tv[rr][7] = v; ti[rr][7] = j;
                                #pragma unroll
                                for (int k = 7; k >= 1; k--) {
                                    const bool sw = tv[rr][k] > tv[rr][k - 1];
                                    const float xv = tv[rr][k]; const int xi = ti[rr][k];
                                    tv[rr][k]     = sw ? tv[rr][k - 1] : tv[rr][k];
                                    ti[rr][k]     = sw ? ti[rr][k - 1] : ti[rr][k];
                                    tv[rr][k - 1] = sw ? xv : tv[rr][k - 1];
                                    ti[rr][k - 1] = sw ? xi : ti[rr][k - 1];
                                }
                            }
                        }
                }
            #pragma unroll
            for (int mf = 0; mf < 2; mf++)
                #pragma unroll
                for (int nn = 0; nn < 8; nn++)
                    #pragma unroll
                    for (int c = 0; c < 4; c++) acc[mf][nn][c] = 0.0f;
        }
    }

    // ---- final merge: 8 lists x 8 entries per row -> top-8 ----
    __syncthreads();
    float* cv = (float*)smem;                 // 128*64 floats = 32KB
    int*   ci = (int*)(smem + 32768);         // 128*64 ints   = 32KB
    #pragma unroll
    for (int mf = 0; mf < 2; mf++)
        #pragma unroll
        for (int h = 0; h < 2; h++) {
            const int rr = mf * 2 + h;
            const int row = wm * 32 + mf * 16 + h * 8 + (lane >> 2);
            const int slot = wn * 32 + (lane & 3) * 8;
            #pragma unroll
            for (int k = 0; k < 8; k++) {
                cv[row * 64 + slot + k] = tv[rr][k];
                ci[row * 64 + slot + k] = ti[rr][k];
            }
        }
    __syncthreads();
    if (t < 128) {
        float bv[8]; int bi[8];
        #pragma unroll
        for (int k = 0; k < 8; k++) { bv[k] = neg_inf(); bi[k] = 0x7FFFFFFF; }
        for (int s = 0; s < 64; s++) {
            const float v = cv[t * 64 + s]; const int i = ci[t * 64 + s];
            if (v > bv[7] || (v == bv[7] && i < bi[7])) {
                bv[7] = v; bi[7] = i;
                #pragma unroll
                for (int k = 7; k >= 1; k--) {
                    const bool sw = (bv[k] > bv[k - 1]) || (bv[k] == bv[k - 1] && bi[k] < bi[k - 1]);
                    const float xv = bv[k]; const int xi = bi[k];
                    bv[k]     = sw ? bv[k - 1] : bv[k];
                    bi[k]     = sw ? bi[k - 1] : bi[k];
                    bv[k - 1] = sw ? xv : bv[k - 1];
                    bi[k - 1] = sw ? xi : bi[k - 1];
                }
            }
        }
        #pragma unroll
        for (int k = 0; k < 8; k++) g_topk[(b * NNODE + i0 + t) * TOPK + k] = bi[k];
    }
}

// ---------------------------------------------------------------------------
// Kernel 3: gather-mean -> GEMM(W^T) -> +bias +residual -> LayerNorm
// ---------------------------------------------------------------------------
#define K3_SMEM ((2 * 32 * 260) * 4 + 256 * 4)

__global__ __launch_bounds__(256, 2) void k_msg_gemm_ln(
    const float* __restrict__ X, const float* __restrict__ bias,
    const float* __restrict__ gamma, const float* __restrict__ beta,
    float* __restrict__ outp)
{
    extern __shared__ float smemf[];
    float* msg = smemf;
    float* Ws  = msg + 32 * 260;
    int* sidx  = (int*)(Ws + 32 * 260);

    const int b = blockIdx.y, n0 = blockIdx.x * 32;
    const int t = threadIdx.x, w = t >> 5, lane = t & 31;
    const float* Xb = X + b * (NNODE * DIM);

    sidx[t] = g_topk[(b * NNODE + n0) * TOPK + t];
    __syncthreads();

    for (int rr = 0; rr < 4; rr++) {
        const int r = w * 4 + rr;
        float4 a0 = make_float4(0,0,0,0), a1 = make_float4(0,0,0,0);
        #pragma unroll
        for (int nb = 0; nb < 8; nb++) {
            const int j = sidx[r * 8 + nb];
            const float4* src = (const float4*)(Xb + j * DIM);
            const float4 v0 = src[lane], v1 = src[lane + 32];
            a0.x += v0.x; a0.y += v0.y; a0.z += v0.z; a0.w += v0.w;
            a1.x += v1.x; a1.y += v1.y; a1.z += v1.z; a1.w += v1.w;
        }
        const float sc = 0.125f;
        a0.x *= sc; a0.y *= sc; a0.z *= sc; a0.w *= sc;
        a1.x *= sc; a1.y *= sc; a1.z *= sc; a1.w *= sc;
        *(float4*)(msg + r * 260 + lane * 4)       = a0;
        *(float4*)(msg + r * 260 + 128 + lane * 4) = a1;
    }

    const int tx = t & 15, ty = t >> 4;
    const int r0 = ty * 2;
    float acc0[16], acc1[16];
    #pragma unroll
    for (int i = 0; i < 16; i++) { acc0[i] = 0.0f; acc1[i] = 0.0f; }

    for (int kc = 0; kc < DIM; kc += 32) {
        __syncthreads();
        #pragma unroll
        for (int s = 0; s < 8; s++) {
            const int lin = t + 256 * s;
            const int e4 = (lin & 63) * 4;
            const int dd = lin >> 6;
            *(float4*)(Ws + dd * 260 + e4) = *(const float4*)(g_Wt + (kc + dd) * DIM + e4);
        }
        __syncthreads();
        #pragma unroll 4
        for (int kk = 0; kk < 32; kk++) {
            const float m0 = msg[r0 * 260 + kc + kk];
            const float m1 = msg[(r0 + 1) * 260 + kc + kk];
            #pragma unroll
            for (int q = 0; q < 4; q++) {
                const float4 wv = *(const float4*)(Ws + kk * 260 + q * 64 + tx * 4);
                acc0[q*4+0] = fmaf(m0, wv.x, acc0[q*4+0]);
                acc0[q*4+1] = fmaf(m0, wv.y, acc0[q*4+1]);
                acc0[q*4+2] = fmaf(m0, wv.z, acc0[q*4+2]);
                acc0[q*4+3] = fmaf(m0, wv.w, acc0[q*4+3]);
                acc1[q*4+0] = fmaf(m1, wv.x, acc1[q*4+0]);
                acc1[q*4+1] = fmaf(m1, wv.y, acc1[q*4+1]);
                acc1[q*4+2] = fmaf(m1, wv.z, acc1[q*4+2]);
                acc1[q*4+3] = fmaf(m1, wv.w, acc1[q*4+3]);
            }
        }
    }

    float z0[16], z1[16];
    #pragma unroll
    for (int q = 0; q < 4; q++) {
        const int e = q * 64 + tx * 4;
        const float4 bb = *(const float4*)(bias + e);
        const float4 x0 = *(const float4*)(Xb + (n0 + r0) * DIM + e);
        const float4 x1 = *(const float4*)(Xb + (n0 + r0 + 1) * DIM + e);
        z0[q*4+0] = acc0[q*4+0] + bb.x + x0.x;
        z0[q*4+1] = acc0[q*4+1] + bb.y + x0.y;
        z0[q*4+2] = acc0[q*4+2] + bb.z + x0.z;
        z0[q*4+3] = acc0[q*4+3] + bb.w + x0.w;
        z1[q*4+0] = acc1[q*4+0] + bb.x + x1.x;
        z1[q*4+1] = acc1[q*4+1] + bb.y + x1.y;
        z1[q*4+2] = acc1[q*4+2] + bb.z + x1.z;
        z1[q*4+3] = acc1[q*4+3] + bb.w + x1.w;
    }
    const unsigned hmask = (t & 16) ? 0xFFFF0000u : 0x0000FFFFu;
    float s0 = 0.0f, s1 = 0.0f;
    #pragma unroll
    for (int i = 0; i < 16; i++) { s0 += z0[i]; s1 += z1[i]; }
    #pragma unroll
    for (int off = 8; off >= 1; off >>= 1) {
        s0 += __shfl_xor_sync(hmask, s0, off);
        s1 += __shfl_xor_sync(hmask, s1, off);
    }
    const float mu0 = s0 * (1.0f / 256.0f), mu1 = s1 * (1.0f / 256.0f);
    float q0 = 0.0f, q1 = 0.0f;
    #pragma unroll
    for (int i = 0; i < 16; i++) {
        const float d0 = z0[i] - mu0; q0 += d0 * d0;
        const float d1 = z1[i] - mu1; q1 += d1 * d1;
    }
    #pragma unroll
    for (int off = 8; off >= 1; off >>= 1) {
        q0 += __shfl_xor_sync(hmask, q0, off);
        q1 += __shfl_xor_sync(hmask, q1, off);
    }
    const float is0 = rsqrtf(q0 * (1.0f / 256.0f) + 1e-5f);
    const float is1 = rsqrtf(q1 * (1.0f / 256.0f) + 1e-5f);
    #pragma unroll
    for (int q = 0; q < 4; q++) {
        const int e = q * 64 + tx * 4;
        const float4 g  = *(const float4*)(gamma + e);
        const float4 be = *(const float4*)(beta + e);
        float4 o0, o1;
        o0.x = (z0[q*4+0] - mu0) * is0 * g.x + be.x;
        o0.y = (z0[q*4+1] - mu0) * is0 * g.y + be.y;
        o0.z = (z0[q*4+2] - mu0) * is0 * g.z + be.z;
        o0.w = (z0[q*4+3] - mu0) * is0 * g.w + be.w;
        o1.x = (z1[q*4+0] - mu1) * is1 * g.x + be.x;
        o1.y = (z1[q*4+1] - mu1) * is1 * g.y + be.y;
        o1.z = (z1[q*4+2] - mu1) * is1 * g.z + be.z;
        o1.w = (z1[q*4+3] - mu1) * is1 * g.w + be.w;
        *(float4*)(outp + (b * NNODE + n0 + r0) * DIM + e)     = o0;
        *(float4*)(outp + (b * NNODE + n0 + r0 + 1) * DIM + e) = o1;
    }
}

// ---------------------------------------------------------------------------
extern "C" void kernel_launch(void* const* d_in, const int* in_sizes, int n_in,
                              void* d_out, int out_size) {
    const float* X     = (const float*)d_in[0];
    const float* W     = (const float*)d_in[1];
    const float* bias  = (const float*)d_in[2];
    const float* gamma = (const float*)d_in[3];
    const float* beta  = (const float*)d_in[4];
    float* outp = (float*)d_out;

    static bool s_attr = false;
    if (!s_attr) {
        cudaFuncSetAttribute(k_sim_topk, cudaFuncAttributeMaxDynamicSharedMemorySize, K2_SMEM);
        cudaFuncSetAttribute(k_msg_gemm_ln, cudaFuncAttributeMaxDynamicSharedMemorySize, K3_SMEM);
        s_attr = true;
    }

    k_norm_split<<<BATCH * NNODE / 8, 256>>>(X);
    k_wt<<<dim3(DIM / 32, DIM / 32), dim3(32, 8)>>>(W);
    k_sim_topk<<<dim3(NNODE / 128, BATCH), 256, K2_SMEM>>>();
    k_msg_gemm_ln<<<dim3(NNODE / 32, BATCH), 256, K3_SMEM>>>(X, bias, gamma, beta, outp);
}